// round 3
// baseline (speedup 1.0000x reference)
#include <cuda_runtime.h>
#include <math.h>

#define NC 128   // clusters
#define ND 64    // dimension

// V_FACTOR = 2*pi^32/(64*31!) — reference multiplies det by this in fp32; the
// product underflows (FTZ -> 0) for tiny dets, which drives the validity mask.
#define V_FACTOR_D 3.080513e-20
#define FLT_MIN_NORMAL 1.1754943508222875e-38

// ---------------- device scratch (no allocations allowed) ----------------
static __device__ __align__(16) float g_mu[NC * ND];
static __device__ __align__(16) float g_S[NC * ND * ND];
static __device__ __align__(16) float g_ZZ[NC * ND * ND];
static __device__ float  g_n[NC];
static __device__ float  g_Gamma[NC];
static __device__ float  g_Vii32[NC];
static __device__ double g_Vii64[NC];
static __device__ float  g_kappa[NC * NC];
static __device__ int    g_active[NC];
static __device__ int    g_sel[NC];
static __device__ int    g_ncand;
static __device__ int    g_cand[128];
static __device__ double g_kval[128];

__device__ __forceinline__ float  f_inf() { return __int_as_float(0x7f800000); }
__device__ __forceinline__ double d_inf() { return __longlong_as_double(0x7ff0000000000000LL); }

// Emulate the reference's fp32 `V_ij = V_FACTOR*det > 0` test under FTZ:
// the product is nonzero only if it reaches the fp32 normal range.
__device__ __forceinline__ bool vij_valid(double det) {
    return (det > 0.0) && (det * V_FACTOR_D >= FLT_MIN_NORMAL);
}

// ---------------------------------------------------------------------------
// Block-parallel 64x64 determinant, pivot-free Gaussian elimination (fp32).
// 128 threads: row = tid>>1, half = tid&1 owns cols [half*32, half*32+32).
// SPD inputs -> unpivoted GE is stable. det accumulated in fp64 on thread 0.
// ---------------------------------------------------------------------------
__device__ double block_det64f(float a[32], float* s_piv) {
    const int tid  = threadIdx.x;
    const int row  = tid >> 1;
    const int half = tid & 1;
    const int c0   = half << 5;
    double det = 1.0;
#pragma unroll
    for (int k = 0; k < 64; ++k) {
        if (row == k) {
#pragma unroll
            for (int q = 0; q < 8; ++q)
                reinterpret_cast<float4*>(s_piv)[half * 8 + q] =
                    make_float4(a[4*q], a[4*q+1], a[4*q+2], a[4*q+3]);
        }
        __syncthreads();
        float pk = s_piv[k];
        if (tid == 0) det *= (double)pk;
        float cand  = a[k & 31];
        float other = __shfl_xor_sync(0xffffffffu, cand, 1);
        float fr    = ((k >> 5) == half) ? cand : other;
        float f     = __fdividef(fr, pk);
        if (row > k && (c0 + 32) > k) {
#pragma unroll
            for (int q = 0; q < 8; ++q) {
                float4 p = reinterpret_cast<const float4*>(s_piv)[half * 8 + q];
                a[4*q]   -= f * p.x;
                a[4*q+1] -= f * p.y;
                a[4*q+2] -= f * p.z;
                a[4*q+3] -= f * p.w;
            }
        }
        __syncthreads();
    }
    return det;
}

// fp64 version — used for Vii and for the argmin candidates.
__device__ double block_det64d(double a[32], double* s_piv) {
    const int tid  = threadIdx.x;
    const int row  = tid >> 1;
    const int half = tid & 1;
    const int c0   = half << 5;
    double det = 1.0;
#pragma unroll
    for (int k = 0; k < 64; ++k) {
        if (row == k) {
#pragma unroll
            for (int q = 0; q < 32; ++q) s_piv[c0 + q] = a[q];
        }
        __syncthreads();
        double pk = s_piv[k];
        if (tid == 0) det *= pk;
        double cand  = a[k & 31];
        double other = __shfl_xor_sync(0xffffffffu, cand, 1);
        double fr    = ((k >> 5) == half) ? cand : other;
        double f     = fr / pk;
        if (row > k && (c0 + 32) > k) {
#pragma unroll
            for (int q = 0; q < 32; ++q) a[q] -= f * s_piv[c0 + q];
        }
        __syncthreads();
    }
    return det;
}

// ---------------------------------------------------------------------------
// K0: copy inputs into working state, init active flags.
// ---------------------------------------------------------------------------
__global__ void k0_init(const float* __restrict__ mu_in, const float* __restrict__ S_in,
                        const float* __restrict__ n_in, const int* __restrict__ cact) {
    const int stride = gridDim.x * blockDim.x;
    const int idx = blockIdx.x * blockDim.x + threadIdx.x;
    const float4* s4 = reinterpret_cast<const float4*>(S_in);
    float4* g4 = reinterpret_cast<float4*>(g_S);
    for (int t = idx; t < NC * ND * ND / 4; t += stride) g4[t] = s4[t];
    const float4* m4 = reinterpret_cast<const float4*>(mu_in);
    float4* gm4 = reinterpret_cast<float4*>(g_mu);
    for (int t = idx; t < NC * ND / 4; t += stride) gm4[t] = m4[t];
    if (idx < NC) {
        g_n[idx] = n_in[idx];
        g_active[idx] = (idx < cact[0]) ? 1 : 0;
    }
}

// ---------------------------------------------------------------------------
// K1: per-cluster d^2 (euclidean, or Mahalanobis via SPD solve when n>=100),
//     Gamma = active ? exp(-d2) : 0.   Reads the ORIGINAL inputs.
// ---------------------------------------------------------------------------
__global__ void k1_gamma(const float* __restrict__ z, const float* __restrict__ mu,
                         const float* __restrict__ S, const float* __restrict__ n,
                         const int* __restrict__ cact) {
    const int c = blockIdx.x;
    const int tid = threadIdx.x;
    __shared__ float sA[64][65];
    __shared__ float s_e[64];
    __shared__ float s_x[64];
    __shared__ float s_d2;
    const float nc = n[c];
    if (tid < 64) s_e[tid] = z[tid] - mu[c * ND + tid];
    __syncthreads();
    if (nc < 100.0f) {
        if (tid < 32) {
            float v = s_e[tid] * s_e[tid] + s_e[tid + 32] * s_e[tid + 32];
#pragma unroll
            for (int off = 16; off; off >>= 1) v += __shfl_down_sync(0xffffffffu, v, off);
            if (tid == 0) s_d2 = v;
        }
        __syncthreads();
    } else {
        const float invn = 1.0f / nc;
        for (int idx = tid; idx < ND * ND; idx += blockDim.x)
            sA[idx >> 6][idx & 63] = S[c * ND * ND + idx] * invn;
        if (tid < 64) s_x[tid] = s_e[tid];
        __syncthreads();
        for (int k = 0; k < 63; ++k) {
            if (tid > k && tid < 64) {
                float f = sA[tid][k] / sA[k][k];
                for (int jj = k + 1; jj < 64; ++jj) sA[tid][jj] -= f * sA[k][jj];
                s_x[tid] -= f * s_x[k];
            }
            __syncthreads();
        }
        for (int k = 63; k >= 0; --k) {
            if (tid < 32) {
                float acc = 0.0f;
                for (int jj = k + 1 + tid; jj < 64; jj += 32) acc += sA[k][jj] * s_x[jj];
#pragma unroll
                for (int off = 16; off; off >>= 1) acc += __shfl_down_sync(0xffffffffu, acc, off);
                if (tid == 0) s_x[k] = (s_x[k] - acc) / sA[k][k];
            }
            __syncthreads();
        }
        if (tid < 32) {
            float v = s_e[tid] * s_x[tid] + s_e[tid + 32] * s_x[tid + 32];
#pragma unroll
            for (int off = 16; off; off >>= 1) v += __shfl_down_sync(0xffffffffu, v, off);
            if (tid == 0) s_d2 = v;
        }
        __syncthreads();
    }
    if (tid == 0)
        g_Gamma[c] = (c < cact[0]) ? expf(-s_d2) : 0.0f;
}

// ---------------------------------------------------------------------------
// K2: argmax Gamma (first occurrence), incremental update or spawn, then sel.
// ---------------------------------------------------------------------------
__global__ void k2_update(const float* __restrict__ z, const int* __restrict__ cact) {
    const int tid = threadIdx.x;
    __shared__ float s_ej[64];
    __shared__ int s_j, s_incr;
    __shared__ float s_nj;
    if (tid == 0) {
        int bj = 0; float bv = g_Gamma[0];
        for (int c2 = 1; c2 < NC; ++c2) {
            float v = g_Gamma[c2];
            if (v > bv) { bv = v; bj = c2; }
        }
        s_j = bj;
        s_incr = (bv > 0.9f) ? 1 : 0;
        s_nj = g_n[bj];
    }
    __syncthreads();
    if (s_incr) {
        const int j = s_j;
        if (tid < 64) s_ej[tid] = z[tid] - g_mu[j * ND + tid];
        __syncthreads();
        if (tid < 64) g_mu[j * ND + tid] += s_ej[tid] / (1.0f + s_nj);
        for (int idx = tid; idx < ND * ND; idx += blockDim.x)
            g_S[j * ND * ND + idx] += s_ej[idx >> 6] * s_ej[idx & 63];
        if (tid == 0) g_n[j] = s_nj + 1.0f;
    } else {
        const int ca = cact[0];
        if (tid < 64) g_mu[ca * ND + tid] = z[tid];
        for (int idx = tid; idx < ND * ND; idx += blockDim.x)
            g_S[ca * ND * ND + idx] = ((idx >> 6) == (idx & 63)) ? 1.0f : 0.0f;
        if (tid == 0) { g_n[ca] = 1.0f; g_Gamma[ca] = 1.0f; g_active[ca] = 1; }
    }
    __syncthreads();
    if (tid < NC)
        g_sel[tid] = (g_Gamma[tid] > (0.9f / 4.0f) && g_active[tid]) ? 1 : 0;
}

// ---------------------------------------------------------------------------
// K3: ZZ = ((n-1)/n) S + mu mu^T (fp32), and Vii = det(S/n) in FP64.
// ---------------------------------------------------------------------------
__global__ void k3_zz_det() {
    const int c = blockIdx.x;
    const int tid = threadIdx.x;
    __shared__ double s_piv[64];
    const float nc   = g_n[c];
    const float coef = (nc - 1.0f) / nc;
    const double invn = 1.0 / (double)nc;
    const float* Sc = &g_S[c * ND * ND];
    const float* mc = &g_mu[c * ND];
    for (int idx = tid; idx < ND * ND; idx += 128)
        g_ZZ[c * ND * ND + idx] = coef * Sc[idx] + mc[idx >> 6] * mc[idx & 63];
    const int row = tid >> 1;
    const int c0  = (tid & 1) << 5;
    double a[32];
    const float* Sr = Sc + row * ND + c0;
#pragma unroll
    for (int q = 0; q < 32; ++q) a[q] = (double)Sr[q] * invn;
    double det = block_det64d(a, s_piv);
    if (tid == 0) { g_Vii64[c] = det; g_Vii32[c] = (float)det; }
}

// ---------------------------------------------------------------------------
// K4 (SCREEN): one block per (i,j). Valid cells build Sigma in fp32 registers
// and take an approximate determinant; kappa32 = det/(det_i+det_j) with the
// reference's fp32-FTZ V_ij>0 validity emulated via vij_valid().
// ---------------------------------------------------------------------------
__global__ void k4_pairs() {
    const int b = blockIdx.x;
    const int i = b >> 7;
    const int j = b & (NC - 1);
    const int tid = threadIdx.x;
    __shared__ __align__(16) float s_piv[64];
    __shared__ float s_muij[64];
    if (i >= j || !g_sel[i] || !g_sel[j]) {
        if (tid == 0) g_kappa[b] = f_inf();
        return;
    }
    const float ni = g_n[i], nj = g_n[j];
    const float nij = ni + nj;
    if (tid < 64)
        s_muij[tid] = (ni * g_mu[i * ND + tid] + nj * g_mu[j * ND + tid]) / nij;
    __syncthreads();
    const float invs = 1.0f / (nij - 1.0f);
    const int row = tid >> 1;
    const int c0  = (tid & 1) << 5;
    const float mr = s_muij[row];
    const float4* zi = reinterpret_cast<const float4*>(&g_ZZ[i * ND * ND + row * ND + c0]);
    const float4* zj = reinterpret_cast<const float4*>(&g_ZZ[j * ND * ND + row * ND + c0]);
    float a[32];
#pragma unroll
    for (int q = 0; q < 8; ++q) {
        float4 x = zi[q];
        float4 y = zj[q];
        a[4*q]   = (x.x + y.x - mr * s_muij[c0 + 4*q])     * invs;
        a[4*q+1] = (x.y + y.y - mr * s_muij[c0 + 4*q + 1]) * invs;
        a[4*q+2] = (x.z + y.z - mr * s_muij[c0 + 4*q + 2]) * invs;
        a[4*q+3] = (x.w + y.w - mr * s_muij[c0 + 4*q + 3]) * invs;
    }
    double det = block_det64f(a, s_piv);
    if (tid == 0)
        g_kappa[b] = vij_valid(det) ? ((float)(det / (double)(g_Vii32[i] + g_Vii32[j])))
                                    : f_inf();
}

// ---------------------------------------------------------------------------
// K5a: kmin of fp32 kappas; collect candidates within a safety margin.
// ---------------------------------------------------------------------------
__global__ void k5a_select() {
    const int tid = threadIdx.x;   // 256
    __shared__ float s_val[256];
    if (tid == 0) g_ncand = 0;
    float bv = f_inf();
    for (int b = tid; b < NC * NC; b += 256) {
        float v = g_kappa[b];
        if (v < bv) bv = v;
    }
    s_val[tid] = bv;
    __syncthreads();
    for (int s = 128; s; s >>= 1) {
        if (tid < s) s_val[tid] = fminf(s_val[tid], s_val[tid + s]);
        __syncthreads();
    }
    const float kmin = s_val[0];
    if (kmin < 3.0e38f) {
        const float thr = kmin + (fabsf(kmin) * 1e-3f);
        for (int b = tid; b < NC * NC; b += 256) {
            if (g_kappa[b] <= thr) {
                int p = atomicAdd(&g_ncand, 1);
                if (p < 128) g_cand[p] = b;
            }
        }
    }
}

// ---------------------------------------------------------------------------
// K5b: fp64 recompute of kappa for each candidate pair (same validity mask).
// ---------------------------------------------------------------------------
__global__ void k5b_refine() {
    const int b = blockIdx.x;
    const int ncand = min(g_ncand, 128);
    if (b >= ncand) return;
    const int tid = threadIdx.x;
    __shared__ double s_piv[64];
    __shared__ double s_muij[64];
    const int flat = g_cand[b];
    const int i = flat >> 7;
    const int j = flat & (NC - 1);
    const double ni = (double)g_n[i], nj = (double)g_n[j];
    const double nij = ni + nj;
    if (tid < 64)
        s_muij[tid] = (ni * (double)g_mu[i * ND + tid] + nj * (double)g_mu[j * ND + tid]) / nij;
    __syncthreads();
    const double invs = 1.0 / (nij - 1.0);
    const int row = tid >> 1;
    const int c0  = (tid & 1) << 5;
    const double mr = s_muij[row];
    const float* zi = &g_ZZ[i * ND * ND + row * ND + c0];
    const float* zj = &g_ZZ[j * ND * ND + row * ND + c0];
    double a[32];
#pragma unroll
    for (int q = 0; q < 32; ++q)
        a[q] = ((double)zi[q] + (double)zj[q] - mr * s_muij[c0 + q]) * invs;
    double det = block_det64d(a, s_piv);
    if (tid == 0)
        g_kval[b] = vij_valid(det) ? (det / (g_Vii64[i] + g_Vii64[j])) : d_inf();
}

// ---------------------------------------------------------------------------
// K5c: argmin over refined candidates (first-flat-index ties, matching
//      jnp.argmin), conditional merge, write out = mu * active.
// ---------------------------------------------------------------------------
__global__ void k5c_final(float* __restrict__ out) {
    const int tid = threadIdx.x;   // 256
    __shared__ double s_val[256];
    __shared__ int    s_idx[256];
    const int ncand = min(g_ncand, 128);
    double bv = d_inf(); int bi = 0x7fffffff;
    for (int b = tid; b < ncand; b += 256) {
        double v = g_kval[b]; int fi = g_cand[b];
        if (v < bv || (v == bv && fi < bi)) { bv = v; bi = fi; }
    }
    s_val[tid] = bv; s_idx[tid] = bi;
    __syncthreads();
    for (int s = 128; s; s >>= 1) {
        if (tid < s) {
            double v2 = s_val[tid + s]; int i2 = s_idx[tid + s];
            if (v2 < s_val[tid] || (v2 == s_val[tid] && i2 < s_idx[tid])) {
                s_val[tid] = v2; s_idx[tid] = i2;
            }
        }
        __syncthreads();
    }
    __shared__ int s_mi, s_mj, s_do;
    __shared__ float s_nmi, s_nmj;
    if (tid == 0) {
        s_do = (s_val[0] < 0.9) ? 1 : 0;
        s_mi = s_idx[0] >> 7;
        s_mj = s_idx[0] & (NC - 1);
        if (s_do) { s_nmi = g_n[s_mi]; s_nmj = g_n[s_mj]; }
    }
    __syncthreads();
    if (s_do) {
        if (tid < 64) {
            const int mi = s_mi, mj = s_mj;
            g_mu[mi * ND + tid] =
                (s_nmi * g_mu[mi * ND + tid] + s_nmj * g_mu[mj * ND + tid]) / (s_nmi + s_nmj);
        }
        if (tid == 0) g_active[s_mj] = 0;
    }
    __syncthreads();
    for (int idx = tid; idx < NC * ND; idx += 256)
        out[idx] = g_active[idx >> 6] ? g_mu[idx] : 0.0f;
}

// ---------------------------------------------------------------------------
extern "C" void kernel_launch(void* const* d_in, const int* in_sizes, int n_in,
                              void* d_out, int out_size) {
    const float* z  = (const float*)d_in[0];
    const float* mu = (const float*)d_in[1];
    const float* S  = (const float*)d_in[2];
    const float* n  = (const float*)d_in[3];
    const int*   ca = (const int*)d_in[4];
    float* out = (float*)d_out;

    k0_init<<<256, 256>>>(mu, S, n, ca);
    k1_gamma<<<NC, 128>>>(z, mu, S, n, ca);
    k2_update<<<1, 256>>>(z, ca);
    k3_zz_det<<<NC, 128>>>();
    k4_pairs<<<NC * NC, 128>>>();
    k5a_select<<<1, 256>>>();
    k5b_refine<<<128, 128>>>();
    k5c_final<<<1, 256>>>(out);
}

// round 5
// speedup vs baseline: 1.3105x; 1.3105x over previous
#include <cuda_runtime.h>
#include <math.h>

#define NC 128   // clusters
#define ND 64    // dimension

// V_FACTOR = 2*pi^32/(64*31!) — reference multiplies det by this in fp32; the
// product underflows (FTZ -> 0) for tiny dets, which drives the validity mask.
#define V_FACTOR_D 3.080513e-20
#define FLT_MIN_NORMAL 1.1754943508222875e-38

// ---------------- device scratch (no allocations allowed) ----------------
static __device__ __align__(16) float g_mu[NC * ND];
static __device__ __align__(16) float g_Smod[ND * ND];   // the one mutated S row
static __device__ __align__(16) float g_ZZ[NC * ND * ND];
static __device__ float  g_n[NC];
static __device__ float  g_Gamma[NC];
static __device__ float  g_Vii32[NC];
static __device__ double g_Vii64[NC];
static __device__ float  g_kappa[NC * NC];
static __device__ int    g_active[NC];
static __device__ int    g_sel[NC];
static __device__ int    g_modidx;
static __device__ int    g_ncand;
static __device__ int    g_cand[128];
static __device__ double g_kval[128];

__device__ __forceinline__ float  f_inf() { return __int_as_float(0x7f800000); }
__device__ __forceinline__ double d_inf() { return __longlong_as_double(0x7ff0000000000000LL); }

// Emulate the reference's fp32 `V_ij = V_FACTOR*det > 0` test under FTZ:
// the product is nonzero only if it reaches the fp32 normal range.
__device__ __forceinline__ bool vij_valid(double det) {
    return (det > 0.0) && (det * V_FACTOR_D >= FLT_MIN_NORMAL);
}

// ---------------------------------------------------------------------------
// fp32 64x64 determinant, pivot-free GE (SPD inputs). 128 threads:
// row = tid>>1, half = tid&1 owns cols [half*32, +32). ONE barrier per step:
// double-buffered pivot rows (row k+1 publishes its updated row into the
// alternate buffer in the same phase). Dead 4-col chunks (entirely left of
// the pivot) are skipped — they never influence the diagonal.
// s_piv: 128 floats (2 buffers). Result valid on thread 0.
// ---------------------------------------------------------------------------
__device__ __forceinline__ double block_det64f(float a[32], float* s_piv) {
    const int tid  = threadIdx.x;
    const int row  = tid >> 1;
    const int half = tid & 1;
    const int c0   = half << 5;
    if (row == 0) {
#pragma unroll
        for (int q = 0; q < 8; ++q)
            reinterpret_cast<float4*>(s_piv)[half * 8 + q] =
                make_float4(a[4*q], a[4*q+1], a[4*q+2], a[4*q+3]);
    }
    __syncthreads();
    double det = 1.0;
#pragma unroll
    for (int k = 0; k < 64; ++k) {
        const float* buf = s_piv + ((k & 1) << 6);
        float pk = buf[k];
        if (tid == 0) det *= (double)pk;
        float cand  = a[k & 31];
        float other = __shfl_xor_sync(0xffffffffu, cand, 1);
        float fr    = ((k >> 5) == half) ? cand : other;
        float f     = __fdividef(fr, pk);
        if (row > k) {
#pragma unroll
            for (int q = 0; q < 8; ++q) {
                if (c0 + 4*q + 3 >= k) {
                    float4 p = reinterpret_cast<const float4*>(buf)[half * 8 + q];
                    a[4*q]   -= f * p.x;
                    a[4*q+1] -= f * p.y;
                    a[4*q+2] -= f * p.z;
                    a[4*q+3] -= f * p.w;
                }
            }
        }
        if (row == k + 1) {
            float* nb = s_piv + (((k + 1) & 1) << 6);
#pragma unroll
            for (int q = 0; q < 8; ++q)
                reinterpret_cast<float4*>(nb)[half * 8 + q] =
                    make_float4(a[4*q], a[4*q+1], a[4*q+2], a[4*q+3]);
        }
        __syncthreads();
    }
    return det;
}

// ---------------------------------------------------------------------------
// fp64 version — only for candidate refinement (few blocks). One fp64 division
// per STEP (pivot owner publishes 1/pk), double2 pivot loads, 1 barrier/step.
// s_piv: 128 doubles, s_inv: 2 doubles.
// ---------------------------------------------------------------------------
__device__ __forceinline__ double block_det64d(double a[32], double* s_piv, double* s_inv) {
    const int tid  = threadIdx.x;
    const int row  = tid >> 1;
    const int half = tid & 1;
    const int c0   = half << 5;
    if (row == 0) {
#pragma unroll
        for (int q = 0; q < 16; ++q)
            reinterpret_cast<double2*>(s_piv)[half * 16 + q] = make_double2(a[2*q], a[2*q+1]);
        if (tid == 0) s_inv[0] = 1.0 / a[0];
    }
    __syncthreads();
    double det = 1.0;
#pragma unroll
    for (int k = 0; k < 64; ++k) {
        const double* buf = s_piv + ((k & 1) << 6);
        double pk  = buf[k];
        double ipk = s_inv[k & 1];
        if (tid == 0) det *= pk;
        double cand  = a[k & 31];
        double other = __shfl_xor_sync(0xffffffffu, cand, 1);
        double fr    = ((k >> 5) == half) ? cand : other;
        double f     = fr * ipk;
        if (row > k) {
#pragma unroll
            for (int q = 0; q < 16; ++q) {
                if (c0 + 2*q + 1 >= k) {
                    double2 p = reinterpret_cast<const double2*>(buf)[half * 16 + q];
                    a[2*q]   -= f * p.x;
                    a[2*q+1] -= f * p.y;
                }
            }
        }
        if (row == k + 1) {
            double* nb = s_piv + (((k + 1) & 1) << 6);
#pragma unroll
            for (int q = 0; q < 16; ++q)
                reinterpret_cast<double2*>(nb)[half * 16 + q] = make_double2(a[2*q], a[2*q+1]);
            if (((k + 1) >> 5) == half) s_inv[(k + 1) & 1] = 1.0 / a[(k + 1) & 31];
        }
        __syncthreads();
    }
    return det;
}

// ---------------------------------------------------------------------------
// K0: copy mu into working state (S is NOT copied — k2 stores a 1-row delta),
// init n and active flags.
// ---------------------------------------------------------------------------
__global__ void k0_init(const float* __restrict__ mu_in, const float* __restrict__ n_in,
                        const int* __restrict__ cact) {
    const int idx = blockIdx.x * blockDim.x + threadIdx.x;
    if (idx < NC * ND / 4)
        reinterpret_cast<float4*>(g_mu)[idx] = reinterpret_cast<const float4*>(mu_in)[idx];
    if (idx < NC) {
        g_n[idx] = n_in[idx];
        g_active[idx] = (idx < cact[0]) ? 1 : 0;
    }
}

// ---------------------------------------------------------------------------
// K1: per-cluster d^2. Euclidean, or Mahalanobis when n>=100 via the LDL^T
// identity e'A^{-1}e = sum_k y_k^2/p_k computed during a SINGLE forward
// elimination pass (register engine, 1 barrier/step, no back-substitution).
// ---------------------------------------------------------------------------
__global__ void k1_gamma(const float* __restrict__ z, const float* __restrict__ mu,
                         const float* __restrict__ S, const float* __restrict__ n,
                         const int* __restrict__ cact) {
    const int c = blockIdx.x;
    const int tid = threadIdx.x;
    __shared__ float s_piv[128];
    __shared__ float s_x[64];
    __shared__ float s_e[64];
    __shared__ float s_d2;
    const float nc = n[c];
    if (tid < 64) s_e[tid] = z[tid] - mu[c * ND + tid];
    __syncthreads();
    if (nc < 100.0f) {
        if (tid < 32) {
            float v = s_e[tid] * s_e[tid] + s_e[tid + 32] * s_e[tid + 32];
#pragma unroll
            for (int off = 16; off; off >>= 1) v += __shfl_down_sync(0xffffffffu, v, off);
            if (tid == 0) s_d2 = v;
        }
        __syncthreads();
    } else {
        const float invn = 1.0f / nc;
        const int row  = tid >> 1;
        const int half = tid & 1;
        const int c0   = half << 5;
        float a[32];
        const float4* Sr = reinterpret_cast<const float4*>(S + c * ND * ND + row * ND + c0);
#pragma unroll
        for (int q = 0; q < 8; ++q) {
            float4 v = Sr[q];
            a[4*q]   = v.x * invn;
            a[4*q+1] = v.y * invn;
            a[4*q+2] = v.z * invn;
            a[4*q+3] = v.w * invn;
        }
        if (tid < 64) s_x[tid] = s_e[tid];
        if (row == 0) {
#pragma unroll
            for (int q = 0; q < 8; ++q)
                reinterpret_cast<float4*>(s_piv)[half * 8 + q] =
                    make_float4(a[4*q], a[4*q+1], a[4*q+2], a[4*q+3]);
        }
        __syncthreads();
        double d2 = 0.0;
#pragma unroll
        for (int k = 0; k < 64; ++k) {
            const float* buf = s_piv + ((k & 1) << 6);
            float pk = buf[k];
            float xk = s_x[k];
            if (tid == 0) d2 += (double)__fdividef(xk * xk, pk);
            float cand  = a[k & 31];
            float other = __shfl_xor_sync(0xffffffffu, cand, 1);
            float fr    = ((k >> 5) == half) ? cand : other;
            float f     = __fdividef(fr, pk);
            if (row > k) {
#pragma unroll
                for (int q = 0; q < 8; ++q) {
                    if (c0 + 4*q + 3 >= k) {
                        float4 p = reinterpret_cast<const float4*>(buf)[half * 8 + q];
                        a[4*q]   -= f * p.x;
                        a[4*q+1] -= f * p.y;
                        a[4*q+2] -= f * p.z;
                        a[4*q+3] -= f * p.w;
                    }
                }
                if (half == 0) s_x[row] -= f * xk;   // one writer per row
            }
            if (row == k + 1) {
                float* nb = s_piv + (((k + 1) & 1) << 6);
#pragma unroll
                for (int q = 0; q < 8; ++q)
                    reinterpret_cast<float4*>(nb)[half * 8 + q] =
                        make_float4(a[4*q], a[4*q+1], a[4*q+2], a[4*q+3]);
            }
            __syncthreads();
        }
        if (tid == 0) s_d2 = (float)d2;
        __syncthreads();
    }
    if (tid == 0)
        g_Gamma[c] = (c < cact[0]) ? expf(-s_d2) : 0.0f;
}

// ---------------------------------------------------------------------------
// K2: argmax Gamma (first occurrence), incremental update or spawn. The S
// mutation is stored as g_Smod + g_modidx (one cluster row only). Then sel.
// ---------------------------------------------------------------------------
__global__ void k2_update(const float* __restrict__ z, const float* __restrict__ S_in,
                          const int* __restrict__ cact) {
    const int tid = threadIdx.x;   // 256
    __shared__ float s_ej[64];
    __shared__ int s_j, s_incr;
    __shared__ float s_nj;
    if (tid == 0) {
        int bj = 0; float bv = g_Gamma[0];
        for (int c2 = 1; c2 < NC; ++c2) {
            float v = g_Gamma[c2];
            if (v > bv) { bv = v; bj = c2; }     // strict >: first max wins
        }
        s_j = bj;
        s_incr = (bv > 0.9f) ? 1 : 0;
        s_nj = g_n[bj];
    }
    __syncthreads();
    if (s_incr) {
        const int j = s_j;
        if (tid < 64) s_ej[tid] = z[tid] - g_mu[j * ND + tid];
        __syncthreads();
        if (tid < 64) g_mu[j * ND + tid] += s_ej[tid] / (1.0f + s_nj);
        for (int idx = tid; idx < ND * ND; idx += 256)
            g_Smod[idx] = S_in[j * ND * ND + idx] + s_ej[idx >> 6] * s_ej[idx & 63];
        if (tid == 0) { g_n[j] = s_nj + 1.0f; g_modidx = j; }
    } else {
        const int ca = cact[0];
        if (tid < 64) g_mu[ca * ND + tid] = z[tid];
        for (int idx = tid; idx < ND * ND; idx += 256)
            g_Smod[idx] = ((idx >> 6) == (idx & 63)) ? 1.0f : 0.0f;
        if (tid == 0) { g_n[ca] = 1.0f; g_Gamma[ca] = 1.0f; g_active[ca] = 1; g_modidx = ca; }
    }
    __syncthreads();
    if (tid < NC)
        g_sel[tid] = (g_Gamma[tid] > 0.225f && g_active[tid]) ? 1 : 0;
}

__device__ __forceinline__ const float* S_eff(const float* S_in, int c) {
    return (c == g_modidx) ? g_Smod : (S_in + c * ND * ND);
}

// ---------------------------------------------------------------------------
// K3: ZZ = ((n-1)/n) S + mu mu^T (float4), and Vii32 = det(S/n) via fp32
// engine (screen only; fp64 Vii is computed lazily for candidates in k5b0).
// ---------------------------------------------------------------------------
__global__ void k3_zz_det(const float* __restrict__ S_in) {
    const int c = blockIdx.x;
    const int tid = threadIdx.x;
    __shared__ float s_piv[128];
    const float nc   = g_n[c];
    const float coef = (nc - 1.0f) / nc;
    const float invn = 1.0f / nc;
    const float* Sc = S_eff(S_in, c);
    const float* mc = &g_mu[c * ND];
    const float4* Sc4 = reinterpret_cast<const float4*>(Sc);
    const float4* mc4 = reinterpret_cast<const float4*>(mc);
    float4* Z4 = reinterpret_cast<float4*>(&g_ZZ[c * ND * ND]);
#pragma unroll
    for (int t = tid; t < ND * ND / 4; t += 128) {
        float4 s = Sc4[t];
        float4 m = mc4[t & 15];
        float mr = mc[t >> 4];
        Z4[t] = make_float4(coef * s.x + mr * m.x, coef * s.y + mr * m.y,
                            coef * s.z + mr * m.z, coef * s.w + mr * m.w);
    }
    const int row = tid >> 1;
    const int c0  = (tid & 1) << 5;
    float a[32];
    const float4* Sr = reinterpret_cast<const float4*>(Sc + row * ND + c0);
#pragma unroll
    for (int q = 0; q < 8; ++q) {
        float4 v = Sr[q];
        a[4*q]   = v.x * invn;
        a[4*q+1] = v.y * invn;
        a[4*q+2] = v.z * invn;
        a[4*q+3] = v.w * invn;
    }
    double det = block_det64f(a, s_piv);
    if (tid == 0) g_Vii32[c] = (float)det;
}

// ---------------------------------------------------------------------------
// K4 (SCREEN): one block per (i,j). Valid cells build Sigma in fp32 registers,
// fast determinant; kappa32 with the reference's FTZ validity emulated.
// ---------------------------------------------------------------------------
__global__ void k4_pairs() {
    const int b = blockIdx.x;
    const int i = b >> 7;
    const int j = b & (NC - 1);
    const int tid = threadIdx.x;
    if (i >= j || !g_sel[i] || !g_sel[j]) {
        if (tid == 0) g_kappa[b] = f_inf();
        return;
    }
    __shared__ float s_piv[128];
    __shared__ float s_muij[64];
    const float ni = g_n[i], nj = g_n[j];
    const float nij = ni + nj;
    if (tid < 64)
        s_muij[tid] = (ni * g_mu[i * ND + tid] + nj * g_mu[j * ND + tid]) / nij;
    __syncthreads();
    const float invs = 1.0f / (nij - 1.0f);
    const int row = tid >> 1;
    const int c0  = (tid & 1) << 5;
    const float mr = s_muij[row];
    const float4* zi = reinterpret_cast<const float4*>(&g_ZZ[i * ND * ND + row * ND + c0]);
    const float4* zj = reinterpret_cast<const float4*>(&g_ZZ[j * ND * ND + row * ND + c0]);
    float a[32];
#pragma unroll
    for (int q = 0; q < 8; ++q) {
        float4 x = zi[q];
        float4 y = zj[q];
        a[4*q]   = (x.x + y.x - mr * s_muij[c0 + 4*q])     * invs;
        a[4*q+1] = (x.y + y.y - mr * s_muij[c0 + 4*q + 1]) * invs;
        a[4*q+2] = (x.z + y.z - mr * s_muij[c0 + 4*q + 2]) * invs;
        a[4*q+3] = (x.w + y.w - mr * s_muij[c0 + 4*q + 3]) * invs;
    }
    double det = block_det64f(a, s_piv);
    if (tid == 0)
        g_kappa[b] = vij_valid(det) ? ((float)(det / (double)(g_Vii32[i] + g_Vii32[j])))
                                    : f_inf();
}

// ---------------------------------------------------------------------------
// K5a: kmin of fp32 kappas; collect candidates within a safety margin.
// ---------------------------------------------------------------------------
__global__ void k5a_select() {
    const int tid = threadIdx.x;   // 256
    __shared__ float s_val[256];
    if (tid == 0) g_ncand = 0;
    float bv = f_inf();
    for (int b = tid; b < NC * NC; b += 256) {
        float v = g_kappa[b];
        if (v < bv) bv = v;
    }
    s_val[tid] = bv;
    __syncthreads();
    for (int s = 128; s; s >>= 1) {
        if (tid < s) s_val[tid] = fminf(s_val[tid], s_val[tid + s]);
        __syncthreads();
    }
    const float kmin = s_val[0];
    if (kmin < 3.0e38f) {
        const float thr = kmin + (fabsf(kmin) * 1e-3f + 1e-30f);
        for (int b = tid; b < NC * NC; b += 256) {
            if (g_kappa[b] <= thr) {
                int p = atomicAdd(&g_ncand, 1);
                if (p < 128) g_cand[p] = b;
            }
        }
    }
}

// ---------------------------------------------------------------------------
// K5b0: fp64 Vii for the clusters referenced by candidates (lazy; few blocks).
// Duplicate writes of identical values are benign.
// ---------------------------------------------------------------------------
__global__ void k5b0_vii(const float* __restrict__ S_in) {
    const int ncand = min(g_ncand, 128);
    const int t = blockIdx.x;
    if (t >= 2 * ncand) return;
    const int flat = g_cand[t >> 1];
    const int c = (t & 1) ? (flat & (NC - 1)) : (flat >> 7);
    const int tid = threadIdx.x;
    __shared__ double s_piv[128];
    __shared__ double s_inv[2];
    const double invn = 1.0 / (double)g_n[c];
    const float* Sc = S_eff(S_in, c);
    const int row = tid >> 1;
    const int c0  = (tid & 1) << 5;
    double a[32];
    const float* Sr = Sc + row * ND + c0;
#pragma unroll
    for (int q = 0; q < 32; ++q) a[q] = (double)Sr[q] * invn;
    double det = block_det64d(a, s_piv, s_inv);
    if (tid == 0) g_Vii64[c] = det;
}

// ---------------------------------------------------------------------------
// K5b: fp64 recompute of kappa for each candidate pair (same validity mask).
// ---------------------------------------------------------------------------
__global__ void k5b_refine() {
    const int b = blockIdx.x;
    const int ncand = min(g_ncand, 128);
    if (b >= ncand) return;
    const int tid = threadIdx.x;
    __shared__ double s_piv[128];
    __shared__ double s_inv[2];
    __shared__ double s_muij[64];
    const int flat = g_cand[b];
    const int i = flat >> 7;
    const int j = flat & (NC - 1);
    const double ni = (double)g_n[i], nj = (double)g_n[j];
    const double nij = ni + nj;
    if (tid < 64)
        s_muij[tid] = (ni * (double)g_mu[i * ND + tid] + nj * (double)g_mu[j * ND + tid]) / nij;
    __syncthreads();
    const double invs = 1.0 / (nij - 1.0);
    const int row = tid >> 1;
    const int c0  = (tid & 1) << 5;
    const double mr = s_muij[row];
    const float* zi = &g_ZZ[i * ND * ND + row * ND + c0];
    const float* zj = &g_ZZ[j * ND * ND + row * ND + c0];
    double a[32];
#pragma unroll
    for (int q = 0; q < 32; ++q)
        a[q] = ((double)zi[q] + (double)zj[q] - mr * s_muij[c0 + q]) * invs;
    double det = block_det64d(a, s_piv, s_inv);
    if (tid == 0)
        g_kval[b] = vij_valid(det) ? (det / (g_Vii64[i] + g_Vii64[j])) : d_inf();
}

// ---------------------------------------------------------------------------
// K5c: argmin over refined candidates (first-flat-index ties, matching
//      jnp.argmin), conditional merge, write out = mu * active.
// ---------------------------------------------------------------------------
__global__ void k5c_final(float* __restrict__ out) {
    const int tid = threadIdx.x;   // 256
    __shared__ double s_val[256];
    __shared__ int    s_idx[256];
    const int ncand = min(g_ncand, 128);
    double bv = d_inf(); int bi = 0x7fffffff;
    for (int b = tid; b < ncand; b += 256) {
        double v = g_kval[b]; int fi = g_cand[b];
        if (v < bv || (v == bv && fi < bi)) { bv = v; bi = fi; }
    }
    s_val[tid] = bv; s_idx[tid] = bi;
    __syncthreads();
    for (int s = 128; s; s >>= 1) {
        if (tid < s) {
            double v2 = s_val[tid + s]; int i2 = s_idx[tid + s];
            if (v2 < s_val[tid] || (v2 == s_val[tid] && i2 < s_idx[tid])) {
                s_val[tid] = v2; s_idx[tid] = i2;
            }
        }
        __syncthreads();
    }
    __shared__ int s_mi, s_mj, s_do;
    __shared__ float s_nmi, s_nmj;
    if (tid == 0) {
        s_do = (s_val[0] < 0.9) ? 1 : 0;
        s_mi = s_idx[0] >> 7;
        s_mj = s_idx[0] & (NC - 1);
        if (s_do) { s_nmi = g_n[s_mi]; s_nmj = g_n[s_mj]; }
    }
    __syncthreads();
    if (s_do) {
        if (tid < 64) {
            const int mi = s_mi, mj = s_mj;
            g_mu[mi * ND + tid] =
                (s_nmi * g_mu[mi * ND + tid] + s_nmj * g_mu[mj * ND + tid]) / (s_nmi + s_nmj);
        }
        if (tid == 0) g_active[s_mj] = 0;
    }
    __syncthreads();
    for (int idx = tid; idx < NC * ND; idx += 256)
        out[idx] = g_active[idx >> 6] ? g_mu[idx] : 0.0f;
}

// ---------------------------------------------------------------------------
extern "C" void kernel_launch(void* const* d_in, const int* in_sizes, int n_in,
                              void* d_out, int out_size) {
    const float* z  = (const float*)d_in[0];
    const float* mu = (const float*)d_in[1];
    const float* S  = (const float*)d_in[2];
    const float* n  = (const float*)d_in[3];
    const int*   ca = (const int*)d_in[4];
    float* out = (float*)d_out;

    k0_init<<<16, 128>>>(mu, n, ca);
    k1_gamma<<<NC, 128>>>(z, mu, S, n, ca);
    k2_update<<<1, 256>>>(z, S, ca);
    k3_zz_det<<<NC, 128>>>(S);
    k4_pairs<<<NC * NC, 128>>>();
    k5a_select<<<1, 256>>>();
    k5b0_vii<<<256, 128>>>(S);
    k5b_refine<<<128, 128>>>();
    k5c_final<<<1, 256>>>(out);
}